// round 1
// baseline (speedup 1.0000x reference)
#include <cuda_runtime.h>
#include <math.h>

// Problem dims (fixed by reference)
#define DIM    1024
#define SEQ    2048
#define BATCH  2
#define NTOK   4096     // BATCH*SEQ
#define NHEAD  16
#define HD     64
#define FF     4096

// ---------------- scratch (static device globals; no allocs allowed) ----------------
__device__ float g_xn  [NTOK * DIM];   // LN1 output
__device__ float g_q   [NTOK * DIM];   // [B,H,S,hd]
__device__ float g_k   [NTOK * DIM];
__device__ float g_v   [NTOK * DIM];
__device__ float g_ctx [NTOK * DIM];   // attention output, [B,S,D]
__device__ float g_res1[NTOK * DIM];   // attn_out + x
__device__ float g_xn2 [NTOK * DIM];   // LN2 output
__device__ float g_h1  [NTOK * FF];    // gelu(ln2@w1+b1)

// ---------------- LayerNorm (ddof=1, matching torch.var unbiased) ----------------
__global__ void ln_kernel(const float* __restrict__ x,
                          const float* __restrict__ scale,
                          const float* __restrict__ shift,
                          float* __restrict__ out)
{
    int row = blockIdx.x;          // 4096 rows
    int t   = threadIdx.x;         // 256 threads, 4 elems each
    const float4* xr = (const float4*)(x + (size_t)row * DIM);
    float4 v = xr[t];
    float s  = v.x + v.y + v.z + v.w;
    float sq = v.x*v.x + v.y*v.y + v.z*v.z + v.w*v.w;
    #pragma unroll
    for (int o = 16; o > 0; o >>= 1) {
        s  += __shfl_xor_sync(0xffffffffu, s,  o);
        sq += __shfl_xor_sync(0xffffffffu, sq, o);
    }
    __shared__ float sbuf[18];
    int w = t >> 5, l = t & 31;
    if (l == 0) { sbuf[w] = s; sbuf[8 + w] = sq; }
    __syncthreads();
    if (t == 0) {
        float ts = 0.f, tq = 0.f;
        #pragma unroll
        for (int i = 0; i < 8; i++) { ts += sbuf[i]; tq += sbuf[8 + i]; }
        float mean = ts * (1.0f / 1024.0f);
        float var  = (tq - 1024.0f * mean * mean) * (1.0f / 1023.0f);
        sbuf[16] = mean;
        sbuf[17] = rsqrtf(var + 1e-5f);
    }
    __syncthreads();
    float mean = sbuf[16], inv = sbuf[17];
    float4 sc = ((const float4*)scale)[t];
    float4 sh = ((const float4*)shift)[t];
    float4 o;
    o.x = (v.x - mean) * inv * sc.x + sh.x;
    o.y = (v.y - mean) * inv * sc.y + sh.y;
    o.z = (v.z - mean) * inv * sc.z + sh.z;
    o.w = (v.w - mean) * inv * sc.w + sh.w;
    ((float4*)(out + (size_t)row * DIM))[t] = o;
}

// ---------------- SGEMM 128x128x8, 8x8 per thread ----------------
// C = A[MxK] @ W[KxN] with epilogue variants.
#define EPI_QKV     0   // head-split store into [B,H,S,hd]
#define EPI_BIASRES 1   // C = acc + bias[n] + resid[row*N+n]
#define EPI_GELU    2   // C = gelu_tanh(acc + bias[n])

__device__ __forceinline__ float gelu_tanh(float x) {
    float t = 0.7978845608028654f * (x + 0.044715f * x * x * x);
    return 0.5f * x * (1.0f + tanhf(t));
}

template<int EPI>
__global__ void __launch_bounds__(256, 2)
gemm_kernel(const float* __restrict__ A, const float* __restrict__ W,
            const float* __restrict__ bias, const float* __restrict__ resid,
            float* __restrict__ C, int M, int N, int K)
{
    __shared__ float As[8][128];
    __shared__ float Bs[8][128];

    int tid = threadIdx.x;
    int bm = blockIdx.y * 128, bn = blockIdx.x * 128;
    int tx = tid & 15, ty = tid >> 4;

    int arow = tid >> 1,  acol = (tid & 1) * 4;    // A tile: 128 rows x 8 cols
    int brow = tid >> 5,  bcol = (tid & 31) * 4;   // B tile: 8 rows x 128 cols

    const float* Aptr = A + (size_t)(bm + arow) * K + acol;
    const float* Bptr = W + (size_t)brow * N + bn + bcol;

    float acc[8][8];
    #pragma unroll
    for (int i = 0; i < 8; i++)
        #pragma unroll
        for (int j = 0; j < 8; j++) acc[i][j] = 0.f;

    for (int k0 = 0; k0 < K; k0 += 8) {
        float4 a4 = *(const float4*)(Aptr + k0);
        float4 b4 = *(const float4*)(Bptr + (size_t)k0 * N);
        As[acol + 0][arow] = a4.x;
        As[acol + 1][arow] = a4.y;
        As[acol + 2][arow] = a4.z;
        As[acol + 3][arow] = a4.w;
        *(float4*)&Bs[brow][bcol] = b4;
        __syncthreads();
        #pragma unroll
        for (int kk = 0; kk < 8; kk++) {
            float af[8], bf[8];
            #pragma unroll
            for (int i = 0; i < 8; i++) af[i] = As[kk][ty * 8 + i];
            #pragma unroll
            for (int j = 0; j < 8; j++) bf[j] = Bs[kk][tx * 8 + j];
            #pragma unroll
            for (int i = 0; i < 8; i++)
                #pragma unroll
                for (int j = 0; j < 8; j++)
                    acc[i][j] += af[i] * bf[j];
        }
        __syncthreads();
    }

    int row0 = bm + ty * 8, col0 = bn + tx * 8;
    #pragma unroll
    for (int i = 0; i < 8; i++) {
        int r = row0 + i;
        #pragma unroll
        for (int j = 0; j < 8; j++) {
            int c = col0 + j;
            float val = acc[i][j];
            if (EPI == EPI_QKV) {
                // row r = b*SEQ + s ; col c = h*HD + d -> [B,H,S,hd]
                int b = r >> 11, s = r & 2047;
                int h = c >> 6,  d = c & 63;
                C[(((size_t)(b * NHEAD + h) * SEQ) + s) * HD + d] = val;
            } else if (EPI == EPI_BIASRES) {
                size_t idx = (size_t)r * N + c;
                C[idx] = val + bias[c] + resid[idx];
            } else { // EPI_GELU
                C[(size_t)r * N + c] = gelu_tanh(val + bias[c]);
            }
        }
    }
}

// ---------------- causal flash attention, 1 thread = 1 query row ----------------
// Q,K,V: [B*H, S, hd].  Output ctx: [B, S, D] (head-interleaved).
__global__ void __launch_bounds__(128)
attn_kernel(const float* __restrict__ Q, const float* __restrict__ K,
            const float* __restrict__ V, float* __restrict__ O)
{
    int bh  = blockIdx.x;                                  // 0..31
    int qb0 = (gridDim.y - 1 - blockIdx.y) * 128;          // heavy blocks first
    int tid = threadIdx.x;
    int qi  = qb0 + tid;

    const float* qptr = Q + ((size_t)bh * SEQ + qi) * HD;
    float qreg[64];
    #pragma unroll
    for (int d = 0; d < 64; d += 4) {
        float4 t4 = *(const float4*)(qptr + d);
        qreg[d] = t4.x; qreg[d+1] = t4.y; qreg[d+2] = t4.z; qreg[d+3] = t4.w;
    }
    float acc[64];
    #pragma unroll
    for (int d = 0; d < 64; d++) acc[d] = 0.f;
    float m = -INFINITY, l = 0.f;

    __shared__ float ksm[32][64];
    __shared__ float vsm[32][64];
    __shared__ float ssm[32][128];   // scores[key_in_tile][thread]

    const float* kbase = K + (size_t)bh * SEQ * HD;
    const float* vbase = V + (size_t)bh * SEQ * HD;
    int kmax = qb0 + 128;

    for (int t0 = 0; t0 < kmax; t0 += 32) {
        // load 32x64 K and V tiles (512 float4 each, 4 per thread)
        #pragma unroll
        for (int u = 0; u < 4; u++) {
            int idx = tid + u * 128;
            int kr = idx >> 4;
            int kc = (idx & 15) * 4;
            *(float4*)&ksm[kr][kc] = *(const float4*)(kbase + (size_t)(t0 + kr) * HD + kc);
            *(float4*)&vsm[kr][kc] = *(const float4*)(vbase + (size_t)(t0 + kr) * HD + kc);
        }
        __syncthreads();

        if (t0 <= qi) {
            float smax = -INFINITY;
            for (int j = 0; j < 32; j++) {
                float s0 = 0.f, s1 = 0.f, s2 = 0.f, s3 = 0.f;
                #pragma unroll
                for (int d = 0; d < 64; d += 4) {
                    s0 += qreg[d    ] * ksm[j][d    ];
                    s1 += qreg[d + 1] * ksm[j][d + 1];
                    s2 += qreg[d + 2] * ksm[j][d + 2];
                    s3 += qreg[d + 3] * ksm[j][d + 3];
                }
                float s = ((s0 + s1) + (s2 + s3)) * 0.125f;
                s = (t0 + j <= qi) ? s : -INFINITY;
                ssm[j][tid] = s;
                smax = fmaxf(smax, s);
            }
            float mnew  = fmaxf(m, smax);
            float scale = __expf(m - mnew);     // m=-inf first time -> 0
            l *= scale;
            #pragma unroll
            for (int d = 0; d < 64; d++) acc[d] *= scale;
            for (int j = 0; j < 32; j++) {
                float p = __expf(ssm[j][tid] - mnew);   // masked -> exp(-inf)=0
                l += p;
                #pragma unroll
                for (int d = 0; d < 64; d++) acc[d] += p * vsm[j][d];
            }
            m = mnew;
        }
        __syncthreads();
    }

    float invl = 1.0f / l;
    int b = bh >> 4, h = bh & 15;
    float* optr = O + ((size_t)(b * SEQ + qi)) * DIM + h * HD;
    #pragma unroll
    for (int d = 0; d < 64; d += 4) {
        float4 o4 = make_float4(acc[d] * invl, acc[d+1] * invl,
                                acc[d+2] * invl, acc[d+3] * invl);
        *(float4*)(optr + d) = o4;
    }
}

// ---------------- launcher ----------------
extern "C" void kernel_launch(void* const* d_in, const int* in_sizes, int n_in,
                              void* d_out, int out_size)
{
    const float* x     = (const float*)d_in[0];
    const float* ln1_s = (const float*)d_in[1];
    const float* ln1_b = (const float*)d_in[2];
    const float* wq    = (const float*)d_in[3];
    const float* wk    = (const float*)d_in[4];
    const float* wv    = (const float*)d_in[5];
    const float* w_out = (const float*)d_in[6];
    const float* b_out = (const float*)d_in[7];
    const float* ln2_s = (const float*)d_in[8];
    const float* ln2_b = (const float*)d_in[9];
    const float* w1    = (const float*)d_in[10];
    const float* b1    = (const float*)d_in[11];
    const float* w2    = (const float*)d_in[12];
    const float* b2    = (const float*)d_in[13];
    float* out = (float*)d_out;

    float *xn, *q, *k, *v, *ctx, *res1, *xn2, *h1;
    cudaGetSymbolAddress((void**)&xn,   g_xn);
    cudaGetSymbolAddress((void**)&q,    g_q);
    cudaGetSymbolAddress((void**)&k,    g_k);
    cudaGetSymbolAddress((void**)&v,    g_v);
    cudaGetSymbolAddress((void**)&ctx,  g_ctx);
    cudaGetSymbolAddress((void**)&res1, g_res1);
    cudaGetSymbolAddress((void**)&xn2,  g_xn2);
    cudaGetSymbolAddress((void**)&h1,   g_h1);

    // 1) LN1
    ln_kernel<<<NTOK, 256>>>(x, ln1_s, ln1_b, xn);

    // 2) QKV projections with head-split store
    dim3 gproj(DIM / 128, NTOK / 128);
    gemm_kernel<EPI_QKV><<<gproj, 256>>>(xn, wq, nullptr, nullptr, q, NTOK, DIM, DIM);
    gemm_kernel<EPI_QKV><<<gproj, 256>>>(xn, wk, nullptr, nullptr, k, NTOK, DIM, DIM);
    gemm_kernel<EPI_QKV><<<gproj, 256>>>(xn, wv, nullptr, nullptr, v, NTOK, DIM, DIM);

    // 3) causal attention
    dim3 gattn(BATCH * NHEAD, SEQ / 128);
    attn_kernel<<<gattn, 128>>>(q, k, v, ctx);

    // 4) out projection + bias + residual(x)
    gemm_kernel<EPI_BIASRES><<<gproj, 256>>>(ctx, w_out, b_out, x, res1, NTOK, DIM, DIM);

    // 5) LN2
    ln_kernel<<<NTOK, 256>>>(res1, ln2_s, ln2_b, xn2);

    // 6) MLP up + GELU
    dim3 gup(FF / 128, NTOK / 128);
    gemm_kernel<EPI_GELU><<<gup, 256>>>(xn2, w1, b1, nullptr, h1, NTOK, FF, DIM);

    // 7) MLP down + bias + residual(res1) -> out
    gemm_kernel<EPI_BIASRES><<<gproj, 256>>>(h1, w2, b2, res1, out, NTOK, DIM, FF);
}

// round 4
// speedup vs baseline: 2.3195x; 2.3195x over previous
#include <cuda_runtime.h>
#include <math.h>
#include <stdint.h>

// Problem dims (fixed by reference)
#define DIM    1024
#define SEQ    2048
#define BATCH  2
#define NTOK   4096     // BATCH*SEQ
#define NHEAD  16
#define HD     64
#define FF     4096

// ---------------- scratch (static device globals; no allocs allowed) ----------------
__device__ float g_xn  [NTOK * DIM];   // LN1 output (tf32-rounded)
__device__ float g_q   [NTOK * DIM];   // [B,H,S,hd]
__device__ float g_k   [NTOK * DIM];
__device__ float g_v   [NTOK * DIM];
__device__ float g_ctx [NTOK * DIM];   // attention output (tf32-rounded)
__device__ float g_res1[NTOK * DIM];   // attn_out + x (full fp32)
__device__ float g_xn2 [NTOK * DIM];   // LN2 output (tf32-rounded)
__device__ float g_h1  [NTOK * FF];    // gelu(...) (tf32-rounded)
__device__ float g_wbuf[12 * 1024 * 1024];  // tf32-rounded weights

// ---------------- PTX helpers ----------------
__device__ __forceinline__ uint32_t smem_u32(const void* p) {
    uint32_t a;
    asm("{ .reg .u64 t; cvta.to.shared.u64 t, %1; cvt.u32.u64 %0, t; }" : "=r"(a) : "l"(p));
    return a;
}
__device__ __forceinline__ float tf32r(float x) {
    float y;
    asm("cvt.rna.tf32.f32 %0, %1;" : "=f"(y) : "f"(x));
    return y;
}
__device__ __forceinline__ void cp_async16(uint32_t dst, const void* src) {
    asm volatile("cp.async.cg.shared.global [%0], [%1], 16;" :: "r"(dst), "l"(src));
}
#define CP_COMMIT() asm volatile("cp.async.commit_group;" ::: "memory")
#define CP_WAIT(n)  asm volatile("cp.async.wait_group %0;" :: "n"(n) : "memory")

__device__ __forceinline__ void ldsm4(uint32_t* r, uint32_t addr) {
    asm volatile("ldmatrix.sync.aligned.m8n8.x4.shared.b16 {%0,%1,%2,%3}, [%4];"
        : "=r"(r[0]), "=r"(r[1]), "=r"(r[2]), "=r"(r[3]) : "r"(addr));
}
__device__ __forceinline__ void mma_tf32(float* d, const uint32_t* a, const uint32_t* b) {
    asm volatile("mma.sync.aligned.m16n8k8.row.col.f32.tf32.tf32.f32 "
                 "{%0,%1,%2,%3}, {%4,%5,%6,%7}, {%8,%9}, {%0,%1,%2,%3};"
                 : "+f"(d[0]), "+f"(d[1]), "+f"(d[2]), "+f"(d[3])
                 : "r"(a[0]), "r"(a[1]), "r"(a[2]), "r"(a[3]), "r"(b[0]), "r"(b[1]));
}
__device__ __forceinline__ uint32_t sw128(uint32_t off) {
    return off ^ ((off >> 3) & 0x70);
}

// ---------------- weight tf32 rounding ----------------
__global__ void round_w(const float4* __restrict__ s, float4* __restrict__ d, int n4) {
    int i = blockIdx.x * 256 + threadIdx.x;
    if (i < n4) {
        float4 v = s[i];
        v.x = tf32r(v.x); v.y = tf32r(v.y); v.z = tf32r(v.z); v.w = tf32r(v.w);
        d[i] = v;
    }
}

// ---------------- LayerNorm (ddof=1), output tf32-rounded ----------------
__global__ void ln_kernel(const float* __restrict__ x,
                          const float* __restrict__ scale,
                          const float* __restrict__ shift,
                          float* __restrict__ out)
{
    int row = blockIdx.x;
    int t   = threadIdx.x;
    const float4* xr = (const float4*)(x + (size_t)row * DIM);
    float4 v = xr[t];
    float s  = v.x + v.y + v.z + v.w;
    float sq = v.x*v.x + v.y*v.y + v.z*v.z + v.w*v.w;
    #pragma unroll
    for (int o = 16; o > 0; o >>= 1) {
        s  += __shfl_xor_sync(0xffffffffu, s,  o);
        sq += __shfl_xor_sync(0xffffffffu, sq, o);
    }
    __shared__ float sbuf[18];
    int w = t >> 5, l = t & 31;
    if (l == 0) { sbuf[w] = s; sbuf[8 + w] = sq; }
    __syncthreads();
    if (t == 0) {
        float ts = 0.f, tq = 0.f;
        #pragma unroll
        for (int i = 0; i < 8; i++) { ts += sbuf[i]; tq += sbuf[8 + i]; }
        float mean = ts * (1.0f / 1024.0f);
        float var  = (tq - 1024.0f * mean * mean) * (1.0f / 1023.0f);
        sbuf[16] = mean;
        sbuf[17] = rsqrtf(var + 1e-5f);
    }
    __syncthreads();
    float mean = sbuf[16], inv = sbuf[17];
    float4 sc = ((const float4*)scale)[t];
    float4 sh = ((const float4*)shift)[t];
    float4 o;
    o.x = tf32r((v.x - mean) * inv * sc.x + sh.x);
    o.y = tf32r((v.y - mean) * inv * sc.y + sh.y);
    o.z = tf32r((v.z - mean) * inv * sc.z + sh.z);
    o.w = tf32r((v.w - mean) * inv * sc.w + sh.w);
    ((float4*)(out + (size_t)row * DIM))[t] = o;
}

// ---------------- TF32 mma.sync GEMM, 128x128 CTA tile, 8 warps ----------------
#define EPI_QKV     0
#define EPI_BIASRES 1
#define EPI_GELU    2

__device__ __forceinline__ float gelu_tanh(float x) {
    float t = 0.7978845608028654f * (x + 0.044715f * x * x * x);
    return 0.5f * x * (1.0f + tanhf(t));
}

// smem: A[2] 128x32 tf32, K-major 128B rows, SW128; B[2] 32x128 n-major, 528B row pitch
#define SM_A(buf)  ((buf) * 16384)
#define SM_B(buf)  (32768 + (buf) * 16896)
#define SM_BYTES   (32768 + 2 * 16896)

template<int EPI>
__device__ __forceinline__ void epi_store(float* __restrict__ C,
                                          const float* __restrict__ bias,
                                          const float* __restrict__ resid,
                                          int N, int r, int c, float v0, float v1)
{
    if (EPI == EPI_QKV) {
        int b = r >> 11, s = r & 2047;
        int h = c >> 6, d = c & 63;
        float* dst = C + (((size_t)(b * NHEAD + h) * SEQ) + s) * HD + d;
        *(float2*)dst = make_float2(v0, v1);
    } else if (EPI == EPI_BIASRES) {
        size_t idx = (size_t)r * N + c;
        *(float2*)(C + idx) = make_float2(v0 + bias[c]     + resid[idx],
                                          v1 + bias[c + 1] + resid[idx + 1]);
    } else { // EPI_GELU (output feeds next GEMM -> round to tf32)
        size_t idx = (size_t)r * N + c;
        *(float2*)(C + idx) = make_float2(tf32r(gelu_tanh(v0 + bias[c])),
                                          tf32r(gelu_tanh(v1 + bias[c + 1])));
    }
}

__device__ __forceinline__ void stage_tiles(uint32_t sb, int buf,
    const float* __restrict__ A, const float* __restrict__ W,
    int bm, int bn, int ch, int K, int N, int tid)
{
    #pragma unroll
    for (int i = 0; i < 4; i++) {
        int idx = tid + (i << 8);
        int row = idx >> 3, c = idx & 7;
        const void* src = A + (size_t)(bm + row) * K + ch * 32 + c * 4;
        cp_async16(sb + SM_A(buf) + sw128(row * 128 + c * 16), src);
    }
    #pragma unroll
    for (int i = 0; i < 4; i++) {
        int idx = tid + (i << 8);
        int row = idx >> 5, c = idx & 31;
        const void* src = W + (size_t)(ch * 32 + row) * N + bn + c * 4;
        cp_async16(sb + SM_B(buf) + row * 528 + c * 16, src);
    }
}

template<int EPI>
__global__ void __launch_bounds__(256)
mma_gemm(const float* __restrict__ A, const float* __restrict__ W,
         const float* __restrict__ bias, const float* __restrict__ resid,
         float* __restrict__ C, int M, int N, int K)
{
    extern __shared__ char smem[];
    uint32_t sb = smem_u32(smem);
    int tid = threadIdx.x, lane = tid & 31, wid = tid >> 5;
    int bm = blockIdx.y * 128, bn = blockIdx.x * 128;
    int wm = (wid >> 2) * 64, wn = (wid & 3) * 32;

    float acc[4][4][4];
    #pragma unroll
    for (int i = 0; i < 4; i++)
        #pragma unroll
        for (int j = 0; j < 4; j++)
            #pragma unroll
            for (int q = 0; q < 4; q++) acc[i][j][q] = 0.f;

    int nch = K >> 5;

    stage_tiles(sb, 0, A, W, bm, bn, 0, K, N, tid);
    CP_COMMIT();

    for (int ch = 0; ch < nch; ch++) {
        int buf = ch & 1;
        if (ch + 1 < nch) {
            stage_tiles(sb, buf ^ 1, A, W, bm, bn, ch + 1, K, N, tid);
            CP_COMMIT();
            CP_WAIT(1);
        } else {
            CP_WAIT(0);
        }
        __syncthreads();

        uint32_t As = sb + SM_A(buf);
        const char* Bs = smem + SM_B(buf);
        int lr = lane & 7, sel = lane >> 3;
        #pragma unroll
        for (int kk = 0; kk < 32; kk += 8) {
            uint32_t a[4][4], b[4][2];
            #pragma unroll
            for (int mt = 0; mt < 4; mt++) {
                int row = wm + mt * 16 + ((sel & 1) << 3) + lr;
                uint32_t ad = As + sw128((uint32_t)(row * 128 + kk * 4 + ((sel >> 1) << 4)));
                ldsm4(a[mt], ad);
            }
            #pragma unroll
            for (int nt = 0; nt < 4; nt++) {
                int col = wn + nt * 8 + (lane >> 2);
                b[nt][0] = *(const uint32_t*)(Bs + (kk + (lane & 3)) * 528 + col * 4);
                b[nt][1] = *(const uint32_t*)(Bs + (kk + 4 + (lane & 3)) * 528 + col * 4);
            }
            #pragma unroll
            for (int mt = 0; mt < 4; mt++)
                #pragma unroll
                for (int nt = 0; nt < 4; nt++)
                    mma_tf32(acc[mt][nt], a[mt], b[nt]);
        }
        __syncthreads();
    }

    // epilogue: c-frag rows r0=base+lane/4, r0+8; cols 2*(lane%4)+{0,1}
    #pragma unroll
    for (int mt = 0; mt < 4; mt++) {
        int r0 = bm + wm + mt * 16 + (lane >> 2);
        #pragma unroll
        for (int nt = 0; nt < 4; nt++) {
            int c0 = bn + wn + nt * 8 + ((lane & 3) << 1);
            epi_store<EPI>(C, bias, resid, N, r0,     c0, acc[mt][nt][0], acc[mt][nt][1]);
            epi_store<EPI>(C, bias, resid, N, r0 + 8, c0, acc[mt][nt][2], acc[mt][nt][3]);
        }
    }
}

// ---------------- causal flash attention, 1 thread = 1 query row ----------------
__global__ void __launch_bounds__(128)
attn_kernel(const float* __restrict__ Q, const float* __restrict__ K,
            const float* __restrict__ V, float* __restrict__ O)
{
    int bh  = blockIdx.x;
    int qb0 = (gridDim.y - 1 - blockIdx.y) * 128;
    int tid = threadIdx.x;
    int qi  = qb0 + tid;

    const float* qptr = Q + ((size_t)bh * SEQ + qi) * HD;
    float qreg[64];
    #pragma unroll
    for (int d = 0; d < 64; d += 4) {
        float4 t4 = *(const float4*)(qptr + d);
        qreg[d] = t4.x; qreg[d+1] = t4.y; qreg[d+2] = t4.z; qreg[d+3] = t4.w;
    }
    float acc[64];
    #pragma unroll
    for (int d = 0; d < 64; d++) acc[d] = 0.f;
    float m = -INFINITY, l = 0.f;

    __shared__ float ksm[32][64];
    __shared__ float vsm[32][64];
    __shared__ float ssm[32][128];

    const float* kbase = K + (size_t)bh * SEQ * HD;
    const float* vbase = V + (size_t)bh * SEQ * HD;
    int kmax = qb0 + 128;

    for (int t0 = 0; t0 < kmax; t0 += 32) {
        #pragma unroll
        for (int u = 0; u < 4; u++) {
            int idx = tid + u * 128;
            int kr = idx >> 4;
            int kc = (idx & 15) * 4;
            *(float4*)&ksm[kr][kc] = *(const float4*)(kbase + (size_t)(t0 + kr) * HD + kc);
            *(float4*)&vsm[kr][kc] = *(const float4*)(vbase + (size_t)(t0 + kr) * HD + kc);
        }
        __syncthreads();

        if (t0 <= qi) {
            float smax = -INFINITY;
            for (int j = 0; j < 32; j++) {
                float s0 = 0.f, s1 = 0.f, s2 = 0.f, s3 = 0.f;
                #pragma unroll
                for (int d = 0; d < 64; d += 4) {
                    s0 += qreg[d    ] * ksm[j][d    ];
                    s1 += qreg[d + 1] * ksm[j][d + 1];
                    s2 += qreg[d + 2] * ksm[j][d + 2];
                    s3 += qreg[d + 3] * ksm[j][d + 3];
                }
                float s = ((s0 + s1) + (s2 + s3)) * 0.125f;
                s = (t0 + j <= qi) ? s : -INFINITY;
                ssm[j][tid] = s;
                smax = fmaxf(smax, s);
            }
            float mnew  = fmaxf(m, smax);
            float scale = __expf(m - mnew);
            l *= scale;
            #pragma unroll
            for (int d = 0; d < 64; d++) acc[d] *= scale;
            for (int j = 0; j < 32; j++) {
                float p = __expf(ssm[j][tid] - mnew);
                l += p;
                #pragma unroll
                for (int d = 0; d < 64; d++) acc[d] += p * vsm[j][d];
            }
            m = mnew;
        }
        __syncthreads();
    }

    float invl = 1.0f / l;
    int b = bh >> 4, h = bh & 15;
    float* optr = O + ((size_t)(b * SEQ + qi)) * DIM + h * HD;
    #pragma unroll
    for (int d = 0; d < 64; d += 4) {
        float4 o4 = make_float4(tf32r(acc[d] * invl),   tf32r(acc[d+1] * invl),
                                tf32r(acc[d+2] * invl), tf32r(acc[d+3] * invl));
        *(float4*)(optr + d) = o4;
    }
}

// ---------------- launcher ----------------
extern "C" void kernel_launch(void* const* d_in, const int* in_sizes, int n_in,
                              void* d_out, int out_size)
{
    const float* x     = (const float*)d_in[0];
    const float* ln1_s = (const float*)d_in[1];
    const float* ln1_b = (const float*)d_in[2];
    const float* wq    = (const float*)d_in[3];
    const float* wk    = (const float*)d_in[4];
    const float* wv    = (const float*)d_in[5];
    const float* w_out = (const float*)d_in[6];
    const float* b_out = (const float*)d_in[7];
    const float* ln2_s = (const float*)d_in[8];
    const float* ln2_b = (const float*)d_in[9];
    const float* w1    = (const float*)d_in[10];
    const float* b1    = (const float*)d_in[11];
    const float* w2    = (const float*)d_in[12];
    const float* b2    = (const float*)d_in[13];
    float* out = (float*)d_out;

    float *xn, *q, *k, *v, *ctx, *res1, *xn2, *h1, *wb;
    cudaGetSymbolAddress((void**)&xn,   g_xn);
    cudaGetSymbolAddress((void**)&q,    g_q);
    cudaGetSymbolAddress((void**)&k,    g_k);
    cudaGetSymbolAddress((void**)&v,    g_v);
    cudaGetSymbolAddress((void**)&ctx,  g_ctx);
    cudaGetSymbolAddress((void**)&res1, g_res1);
    cudaGetSymbolAddress((void**)&xn2,  g_xn2);
    cudaGetSymbolAddress((void**)&h1,   g_h1);
    cudaGetSymbolAddress((void**)&wb,   g_wbuf);

    float* wq_r = wb + 0 * 1048576;
    float* wk_r = wb + 1 * 1048576;
    float* wv_r = wb + 2 * 1048576;
    float* wo_r = wb + 3 * 1048576;
    float* w1_r = wb + 4 * 1048576;   // 4M
    float* w2_r = wb + 8 * 1048576;   // 4M

    cudaFuncSetAttribute(mma_gemm<EPI_QKV>,     cudaFuncAttributeMaxDynamicSharedMemorySize, SM_BYTES);
    cudaFuncSetAttribute(mma_gemm<EPI_BIASRES>, cudaFuncAttributeMaxDynamicSharedMemorySize, SM_BYTES);
    cudaFuncSetAttribute(mma_gemm<EPI_GELU>,    cudaFuncAttributeMaxDynamicSharedMemorySize, SM_BYTES);

    // 0) round weights to tf32 once
    round_w<<<1024, 256>>>((const float4*)wq,    (float4*)wq_r, 262144);
    round_w<<<1024, 256>>>((const float4*)wk,    (float4*)wk_r, 262144);
    round_w<<<1024, 256>>>((const float4*)wv,    (float4*)wv_r, 262144);
    round_w<<<1024, 256>>>((const float4*)w_out, (float4*)wo_r, 262144);
    round_w<<<4096, 256>>>((const float4*)w1,    (float4*)w1_r, 1048576);
    round_w<<<4096, 256>>>((const float4*)w2,    (float4*)w2_r, 1048576);

    // 1) LN1 (tf32-rounded output)
    ln_kernel<<<NTOK, 256>>>(x, ln1_s, ln1_b, xn);

    // 2) QKV projections with head-split store
    dim3 gproj(DIM / 128, NTOK / 128);
    mma_gemm<EPI_QKV><<<gproj, 256, SM_BYTES>>>(xn, wq_r, nullptr, nullptr, q, NTOK, DIM, DIM);
    mma_gemm<EPI_QKV><<<gproj, 256, SM_BYTES>>>(xn, wk_r, nullptr, nullptr, k, NTOK, DIM, DIM);
    mma_gemm<EPI_QKV><<<gproj, 256, SM_BYTES>>>(xn, wv_r, nullptr, nullptr, v, NTOK, DIM, DIM);

    // 3) causal attention (output tf32-rounded)
    dim3 gattn(BATCH * NHEAD, SEQ / 128);
    attn_kernel<<<gattn, 128>>>(q, k, v, ctx);

    // 4) out projection + bias + residual(x)
    mma_gemm<EPI_BIASRES><<<gproj, 256, SM_BYTES>>>(ctx, wo_r, b_out, x, res1, NTOK, DIM, DIM);

    // 5) LN2
    ln_kernel<<<NTOK, 256>>>(res1, ln2_s, ln2_b, xn2);

    // 6) MLP up + GELU (output tf32-rounded)
    dim3 gup(FF / 128, NTOK / 128);
    mma_gemm<EPI_GELU><<<gup, 256, SM_BYTES>>>(xn2, w1_r, b1, nullptr, h1, NTOK, FF, DIM);

    // 7) MLP down + bias + residual(res1) -> out
    mma_gemm<EPI_BIASRES><<<gproj, 256, SM_BYTES>>>(h1, w2_r, b2, res1, out, NTOK, DIM, FF);
}

// round 5
// speedup vs baseline: 3.9405x; 1.6989x over previous
#include <cuda_runtime.h>
#include <math.h>
#include <stdint.h>

// Problem dims (fixed by reference)
#define DIM    1024
#define SEQ    2048
#define BATCH  2
#define NTOK   4096     // BATCH*SEQ
#define NHEAD  16
#define HD     64
#define FF     4096

// ---------------- scratch (static device globals; no allocs allowed) ----------------
__device__ float g_xn  [NTOK * DIM];   // LN1 output (tf32-rounded)
__device__ float g_q   [NTOK * DIM];   // [B,H,S,hd] (tf32-rounded)
__device__ float g_k   [NTOK * DIM];
__device__ float g_v   [NTOK * DIM];
__device__ float g_ctx [NTOK * DIM];   // attention output (tf32-rounded)
__device__ float g_res1[NTOK * DIM];   // attn_out + x (full fp32)
__device__ float g_xn2 [NTOK * DIM];   // LN2 output (tf32-rounded)
__device__ float g_h1  [NTOK * FF];    // gelu(...) (tf32-rounded)
__device__ float g_wbuf[12 * 1024 * 1024];  // tf32-rounded weights

// ---------------- PTX helpers ----------------
__device__ __forceinline__ uint32_t smem_u32(const void* p) {
    uint32_t a;
    asm("{ .reg .u64 t; cvta.to.shared.u64 t, %1; cvt.u32.u64 %0, t; }" : "=r"(a) : "l"(p));
    return a;
}
__device__ __forceinline__ float tf32r(float x) {
    float y;
    asm("cvt.rna.tf32.f32 %0, %1;" : "=f"(y) : "f"(x));
    return y;
}
__device__ __forceinline__ void cp_async16(uint32_t dst, const void* src) {
    asm volatile("cp.async.cg.shared.global [%0], [%1], 16;" :: "r"(dst), "l"(src));
}
#define CP_COMMIT() asm volatile("cp.async.commit_group;" ::: "memory")
#define CP_WAIT(n)  asm volatile("cp.async.wait_group %0;" :: "n"(n) : "memory")

__device__ __forceinline__ void ldsm4(uint32_t* r, uint32_t addr) {
    asm volatile("ldmatrix.sync.aligned.m8n8.x4.shared.b16 {%0,%1,%2,%3}, [%4];"
        : "=r"(r[0]), "=r"(r[1]), "=r"(r[2]), "=r"(r[3]) : "r"(addr));
}
__device__ __forceinline__ void mma_tf32(float* d, const uint32_t* a, const uint32_t* b) {
    asm volatile("mma.sync.aligned.m16n8k8.row.col.f32.tf32.tf32.f32 "
                 "{%0,%1,%2,%3}, {%4,%5,%6,%7}, {%8,%9}, {%0,%1,%2,%3};"
                 : "+f"(d[0]), "+f"(d[1]), "+f"(d[2]), "+f"(d[3])
                 : "r"(a[0]), "r"(a[1]), "r"(a[2]), "r"(a[3]), "r"(b[0]), "r"(b[1]));
}
__device__ __forceinline__ uint32_t sw128(uint32_t off) {
    return off ^ ((off >> 3) & 0x70);
}

// ---------------- weight tf32 rounding ----------------
__global__ void round_w(const float4* __restrict__ s, float4* __restrict__ d, int n4) {
    int i = blockIdx.x * 256 + threadIdx.x;
    if (i < n4) {
        float4 v = s[i];
        v.x = tf32r(v.x); v.y = tf32r(v.y); v.z = tf32r(v.z); v.w = tf32r(v.w);
        d[i] = v;
    }
}

// ---------------- LayerNorm (ddof=1), output tf32-rounded ----------------
__global__ void ln_kernel(const float* __restrict__ x,
                          const float* __restrict__ scale,
                          const float* __restrict__ shift,
                          float* __restrict__ out)
{
    int row = blockIdx.x;
    int t   = threadIdx.x;
    const float4* xr = (const float4*)(x + (size_t)row * DIM);
    float4 v = xr[t];
    float s  = v.x + v.y + v.z + v.w;
    float sq = v.x*v.x + v.y*v.y + v.z*v.z + v.w*v.w;
    #pragma unroll
    for (int o = 16; o > 0; o >>= 1) {
        s  += __shfl_xor_sync(0xffffffffu, s,  o);
        sq += __shfl_xor_sync(0xffffffffu, sq, o);
    }
    __shared__ float sbuf[18];
    int w = t >> 5, l = t & 31;
    if (l == 0) { sbuf[w] = s; sbuf[8 + w] = sq; }
    __syncthreads();
    if (t == 0) {
        float ts = 0.f, tq = 0.f;
        #pragma unroll
        for (int i = 0; i < 8; i++) { ts += sbuf[i]; tq += sbuf[8 + i]; }
        float mean = ts * (1.0f / 1024.0f);
        float var  = (tq - 1024.0f * mean * mean) * (1.0f / 1023.0f);
        sbuf[16] = mean;
        sbuf[17] = rsqrtf(var + 1e-5f);
    }
    __syncthreads();
    float mean = sbuf[16], inv = sbuf[17];
    float4 sc = ((const float4*)scale)[t];
    float4 sh = ((const float4*)shift)[t];
    float4 o;
    o.x = tf32r((v.x - mean) * inv * sc.x + sh.x);
    o.y = tf32r((v.y - mean) * inv * sc.y + sh.y);
    o.z = tf32r((v.z - mean) * inv * sc.z + sh.z);
    o.w = tf32r((v.w - mean) * inv * sc.w + sh.w);
    ((float4*)(out + (size_t)row * DIM))[t] = o;
}

// ---------------- TF32 mma.sync GEMM, 128x128 CTA tile, 8 warps ----------------
#define EPI_QKV     0
#define EPI_BIASRES 1
#define EPI_GELU    2

__device__ __forceinline__ float gelu_tanh(float x) {
    float t = 0.7978845608028654f * (x + 0.044715f * x * x * x);
    return 0.5f * x * (1.0f + tanhf(t));
}

// smem: A[2] 128x32 tf32, K-major 128B rows, SW128; B[2] 32x128 n-major, 528B row pitch
#define SM_A(buf)  ((buf) * 16384)
#define SM_B(buf)  (32768 + (buf) * 16896)
#define SM_BYTES   (32768 + 2 * 16896)

template<int EPI>
__device__ __forceinline__ void epi_store(float* __restrict__ C,
                                          const float* __restrict__ bias,
                                          const float* __restrict__ resid,
                                          int N, int r, int c, float v0, float v1)
{
    if (EPI == EPI_QKV) {
        int b = r >> 11, s = r & 2047;
        int h = c >> 6, d = c & 63;
        float* dst = C + (((size_t)(b * NHEAD + h) * SEQ) + s) * HD + d;
        *(float2*)dst = make_float2(tf32r(v0), tf32r(v1));   // feeds tf32 mma attention
    } else if (EPI == EPI_BIASRES) {
        size_t idx = (size_t)r * N + c;
        *(float2*)(C + idx) = make_float2(v0 + bias[c]     + resid[idx],
                                          v1 + bias[c + 1] + resid[idx + 1]);
    } else { // EPI_GELU (output feeds next GEMM -> round to tf32)
        size_t idx = (size_t)r * N + c;
        *(float2*)(C + idx) = make_float2(tf32r(gelu_tanh(v0 + bias[c])),
                                          tf32r(gelu_tanh(v1 + bias[c + 1])));
    }
}

__device__ __forceinline__ void stage_tiles(uint32_t sb, int buf,
    const float* __restrict__ A, const float* __restrict__ W,
    int bm, int bn, int ch, int K, int N, int tid)
{
    #pragma unroll
    for (int i = 0; i < 4; i++) {
        int idx = tid + (i << 8);
        int row = idx >> 3, c = idx & 7;
        const void* src = A + (size_t)(bm + row) * K + ch * 32 + c * 4;
        cp_async16(sb + SM_A(buf) + sw128(row * 128 + c * 16), src);
    }
    #pragma unroll
    for (int i = 0; i < 4; i++) {
        int idx = tid + (i << 8);
        int row = idx >> 5, c = idx & 31;
        const void* src = W + (size_t)(ch * 32 + row) * N + bn + c * 4;
        cp_async16(sb + SM_B(buf) + row * 528 + c * 16, src);
    }
}

template<int EPI>
__global__ void __launch_bounds__(256)
mma_gemm(const float* __restrict__ A, const float* __restrict__ W,
         const float* __restrict__ bias, const float* __restrict__ resid,
         float* __restrict__ C, int M, int N, int K)
{
    extern __shared__ char smem[];
    uint32_t sb = smem_u32(smem);
    int tid = threadIdx.x, lane = tid & 31, wid = tid >> 5;
    int bm = blockIdx.y * 128, bn = blockIdx.x * 128;
    int wm = (wid >> 2) * 64, wn = (wid & 3) * 32;

    float acc[4][4][4];
    #pragma unroll
    for (int i = 0; i < 4; i++)
        #pragma unroll
        for (int j = 0; j < 4; j++)
            #pragma unroll
            for (int q = 0; q < 4; q++) acc[i][j][q] = 0.f;

    int nch = K >> 5;

    stage_tiles(sb, 0, A, W, bm, bn, 0, K, N, tid);
    CP_COMMIT();

    for (int ch = 0; ch < nch; ch++) {
        int buf = ch & 1;
        if (ch + 1 < nch) {
            stage_tiles(sb, buf ^ 1, A, W, bm, bn, ch + 1, K, N, tid);
            CP_COMMIT();
            CP_WAIT(1);
        } else {
            CP_WAIT(0);
        }
        __syncthreads();

        uint32_t As = sb + SM_A(buf);
        const char* Bs = smem + SM_B(buf);
        int lr = lane & 7, sel = lane >> 3;
        #pragma unroll
        for (int kk = 0; kk < 32; kk += 8) {
            uint32_t a[4][4], b[4][2];
            #pragma unroll
            for (int mt = 0; mt < 4; mt++) {
                int row = wm + mt * 16 + ((sel & 1) << 3) + lr;
                uint32_t ad = As + sw128((uint32_t)(row * 128 + kk * 4 + ((sel >> 1) << 4)));
                ldsm4(a[mt], ad);
            }
            #pragma unroll
            for (int nt = 0; nt < 4; nt++) {
                int col = wn + nt * 8 + (lane >> 2);
                b[nt][0] = *(const uint32_t*)(Bs + (kk + (lane & 3)) * 528 + col * 4);
                b[nt][1] = *(const uint32_t*)(Bs + (kk + 4 + (lane & 3)) * 528 + col * 4);
            }
            #pragma unroll
            for (int mt = 0; mt < 4; mt++)
                #pragma unroll
                for (int nt = 0; nt < 4; nt++)
                    mma_tf32(acc[mt][nt], a[mt], b[nt]);
        }
        __syncthreads();
    }

    #pragma unroll
    for (int mt = 0; mt < 4; mt++) {
        int r0 = bm + wm + mt * 16 + (lane >> 2);
        #pragma unroll
        for (int nt = 0; nt < 4; nt++) {
            int c0 = bn + wn + nt * 8 + ((lane & 3) << 1);
            epi_store<EPI>(C, bias, resid, N, r0,     c0, acc[mt][nt][0], acc[mt][nt][1]);
            epi_store<EPI>(C, bias, resid, N, r0 + 8, c0, acc[mt][nt][2], acc[mt][nt][3]);
        }
    }
}

// ---------------- tf32 mma flash attention ----------------
// 1 CTA = 64 q rows of one (b,h); 4 warps, 16 rows each; Bc=64, double-buffered K/V.
// smem float pitches: Q/K/P = 68 (conflict-free frag loads), V = 72.
#define ATT_QS      0
#define ATT_KS(b)   (17408 + (b) * 17408)
#define ATT_VS(b)   (52224 + (b) * 18432)
#define ATT_PS      89088
#define ATT_BYTES   106496

__global__ void __launch_bounds__(128)
fa_kernel(const float* __restrict__ Q, const float* __restrict__ K,
          const float* __restrict__ V, float* __restrict__ O)
{
    extern __shared__ char smem[];
    uint32_t sb = smem_u32(smem);
    float* sf = (float*)smem;
    int bh = blockIdx.x;
    int qt = gridDim.y - 1 - blockIdx.y;      // heavy blocks first
    int qb = qt * 64;
    int tid = threadIdx.x, lane = tid & 31, w = tid >> 5;
    int r0 = lane >> 2, qr = lane & 3;

    const float* qg = Q + ((size_t)bh * SEQ + qb) * HD;
    const float* kg = K + (size_t)bh * SEQ * HD;
    const float* vg = V + (size_t)bh * SEQ * HD;

    // stage Q tile + K/V tile 0
    #pragma unroll
    for (int i = 0; i < 8; i++) {
        int idx = tid + (i << 7);
        int row = idx >> 4, c4 = (idx & 15) << 2;
        cp_async16(sb + ATT_QS + (row * 68 + c4) * 4, qg + row * 64 + c4);
    }
    #pragma unroll
    for (int i = 0; i < 8; i++) {
        int idx = tid + (i << 7);
        int row = idx >> 4, c4 = (idx & 15) << 2;
        cp_async16(sb + ATT_KS(0) + (row * 68 + c4) * 4, kg + row * 64 + c4);
        cp_async16(sb + ATT_VS(0) + (row * 72 + c4) * 4, vg + row * 64 + c4);
    }
    CP_COMMIT();

    float o[8][4];
    #pragma unroll
    for (int nt = 0; nt < 8; nt++)
        #pragma unroll
        for (int j = 0; j < 4; j++) o[nt][j] = 0.f;
    float m0 = -INFINITY, m1 = -INFINITY, l0 = 0.f, l1 = 0.f;

    int ra = w * 16 + r0;          // local q row (first of pair)
    int ntile = qt + 1;

    for (int t = 0; t < ntile; t++) {
        int buf = t & 1;
        if (t + 1 < ntile) {
            int tn = (t + 1) * 64;
            #pragma unroll
            for (int i = 0; i < 8; i++) {
                int idx = tid + (i << 7);
                int row = idx >> 4, c4 = (idx & 15) << 2;
                cp_async16(sb + ATT_KS(buf ^ 1) + (row * 68 + c4) * 4, kg + (size_t)(tn + row) * 64 + c4);
                cp_async16(sb + ATT_VS(buf ^ 1) + (row * 72 + c4) * 4, vg + (size_t)(tn + row) * 64 + c4);
            }
            CP_COMMIT();
            CP_WAIT(1);
        } else {
            CP_WAIT(0);
        }
        __syncthreads();

        const float* Qs = sf + (ATT_QS >> 2);
        const float* Ks = sf + (ATT_KS(buf) >> 2);
        const float* Vs = sf + (ATT_VS(buf) >> 2);
        float* Ps = sf + (ATT_PS >> 2);

        // ---- S = Q @ K^T ----
        float s[8][4];
        #pragma unroll
        for (int nt = 0; nt < 8; nt++)
            #pragma unroll
            for (int j = 0; j < 4; j++) s[nt][j] = 0.f;

        #pragma unroll
        for (int kk = 0; kk < 64; kk += 8) {
            uint32_t a[4];
            a[0] = __float_as_uint(Qs[ra * 68 + kk + qr]);
            a[1] = __float_as_uint(Qs[(ra + 8) * 68 + kk + qr]);
            a[2] = __float_as_uint(Qs[ra * 68 + kk + qr + 4]);
            a[3] = __float_as_uint(Qs[(ra + 8) * 68 + kk + qr + 4]);
            #pragma unroll
            for (int nt = 0; nt < 8; nt++) {
                uint32_t b[2];
                b[0] = __float_as_uint(Ks[(nt * 8 + r0) * 68 + kk + qr]);
                b[1] = __float_as_uint(Ks[(nt * 8 + r0) * 68 + kk + qr + 4]);
                mma_tf32(s[nt], a, b);
            }
        }

        // ---- mask (diag tile), scale, online softmax ----
        int t0 = t * 64;
        int rq0 = qb + ra, rq1 = rq0 + 8;
        bool diag = (t == qt);
        float tm0 = -INFINITY, tm1 = -INFINITY;
        #pragma unroll
        for (int nt = 0; nt < 8; nt++) {
            int c = t0 + nt * 8 + (qr << 1);
            if (diag) {
                if (c     > rq0) s[nt][0] = -INFINITY;
                if (c + 1 > rq0) s[nt][1] = -INFINITY;
                if (c     > rq1) s[nt][2] = -INFINITY;
                if (c + 1 > rq1) s[nt][3] = -INFINITY;
            }
            s[nt][0] *= 0.125f; s[nt][1] *= 0.125f;
            s[nt][2] *= 0.125f; s[nt][3] *= 0.125f;
            tm0 = fmaxf(tm0, fmaxf(s[nt][0], s[nt][1]));
            tm1 = fmaxf(tm1, fmaxf(s[nt][2], s[nt][3]));
        }
        tm0 = fmaxf(tm0, __shfl_xor_sync(0xffffffffu, tm0, 1));
        tm0 = fmaxf(tm0, __shfl_xor_sync(0xffffffffu, tm0, 2));
        tm1 = fmaxf(tm1, __shfl_xor_sync(0xffffffffu, tm1, 1));
        tm1 = fmaxf(tm1, __shfl_xor_sync(0xffffffffu, tm1, 2));

        float mn0 = fmaxf(m0, tm0), mn1 = fmaxf(m1, tm1);
        float al0 = __expf(m0 - mn0), al1 = __expf(m1 - mn1);
        m0 = mn0; m1 = mn1;

        float ps0 = 0.f, ps1 = 0.f;
        #pragma unroll
        for (int nt = 0; nt < 8; nt++) {
            float p0 = __expf(s[nt][0] - mn0);
            float p1 = __expf(s[nt][1] - mn0);
            float p2 = __expf(s[nt][2] - mn1);
            float p3 = __expf(s[nt][3] - mn1);
            ps0 += p0 + p1; ps1 += p2 + p3;
            int c2 = nt * 8 + (qr << 1);
            *(float2*)&Ps[ra * 68 + c2]       = make_float2(tf32r(p0), tf32r(p1));
            *(float2*)&Ps[(ra + 8) * 68 + c2] = make_float2(tf32r(p2), tf32r(p3));
        }
        ps0 += __shfl_xor_sync(0xffffffffu, ps0, 1);
        ps0 += __shfl_xor_sync(0xffffffffu, ps0, 2);
        ps1 += __shfl_xor_sync(0xffffffffu, ps1, 1);
        ps1 += __shfl_xor_sync(0xffffffffu, ps1, 2);
        l0 = l0 * al0 + ps0;
        l1 = l1 * al1 + ps1;

        #pragma unroll
        for (int nt = 0; nt < 8; nt++) {
            o[nt][0] *= al0; o[nt][1] *= al0;
            o[nt][2] *= al1; o[nt][3] *= al1;
        }
        __syncwarp();

        // ---- O += P @ V ----
        #pragma unroll
        for (int kk = 0; kk < 64; kk += 8) {
            uint32_t a[4];
            a[0] = __float_as_uint(Ps[ra * 68 + kk + qr]);
            a[1] = __float_as_uint(Ps[(ra + 8) * 68 + kk + qr]);
            a[2] = __float_as_uint(Ps[ra * 68 + kk + qr + 4]);
            a[3] = __float_as_uint(Ps[(ra + 8) * 68 + kk + qr + 4]);
            #pragma unroll
            for (int nt = 0; nt < 8; nt++) {
                uint32_t b[2];
                b[0] = __float_as_uint(Vs[(kk + qr) * 72 + nt * 8 + r0]);
                b[1] = __float_as_uint(Vs[(kk + 4 + qr) * 72 + nt * 8 + r0]);
                mma_tf32(o[nt], a, b);
            }
        }
        __syncthreads();
    }

    // ---- epilogue: O /= l, head-interleaved store into [B,S,D], tf32-rounded ----
    float i0 = 1.0f / l0, i1 = 1.0f / l1;
    int b = bh >> 4, h = bh & 15;
    int q0 = qb + ra;
    float* op0 = O + ((size_t)(b * SEQ + q0)) * DIM + h * 64;
    float* op1 = op0 + 8 * DIM;
    #pragma unroll
    for (int nt = 0; nt < 8; nt++) {
        int c = nt * 8 + (qr << 1);
        *(float2*)(op0 + c) = make_float2(tf32r(o[nt][0] * i0), tf32r(o[nt][1] * i0));
        *(float2*)(op1 + c) = make_float2(tf32r(o[nt][2] * i1), tf32r(o[nt][3] * i1));
    }
}

// ---------------- launcher ----------------
extern "C" void kernel_launch(void* const* d_in, const int* in_sizes, int n_in,
                              void* d_out, int out_size)
{
    const float* x     = (const float*)d_in[0];
    const float* ln1_s = (const float*)d_in[1];
    const float* ln1_b = (const float*)d_in[2];
    const float* wq    = (const float*)d_in[3];
    const float* wk    = (const float*)d_in[4];
    const float* wv    = (const float*)d_in[5];
    const float* w_out = (const float*)d_in[6];
    const float* b_out = (const float*)d_in[7];
    const float* ln2_s = (const float*)d_in[8];
    const float* ln2_b = (const float*)d_in[9];
    const float* w1    = (const float*)d_in[10];
    const float* b1    = (const float*)d_in[11];
    const float* w2    = (const float*)d_in[12];
    const float* b2    = (const float*)d_in[13];
    float* out = (float*)d_out;

    float *xn, *q, *k, *v, *ctx, *res1, *xn2, *h1, *wb;
    cudaGetSymbolAddress((void**)&xn,   g_xn);
    cudaGetSymbolAddress((void**)&q,    g_q);
    cudaGetSymbolAddress((void**)&k,    g_k);
    cudaGetSymbolAddress((void**)&v,    g_v);
    cudaGetSymbolAddress((void**)&ctx,  g_ctx);
    cudaGetSymbolAddress((void**)&res1, g_res1);
    cudaGetSymbolAddress((void**)&xn2,  g_xn2);
    cudaGetSymbolAddress((void**)&h1,   g_h1);
    cudaGetSymbolAddress((void**)&wb,   g_wbuf);

    float* wq_r = wb + 0 * 1048576;
    float* wk_r = wb + 1 * 1048576;
    float* wv_r = wb + 2 * 1048576;
    float* wo_r = wb + 3 * 1048576;
    float* w1_r = wb + 4 * 1048576;
    float* w2_r = wb + 8 * 1048576;

    cudaFuncSetAttribute(mma_gemm<EPI_QKV>,     cudaFuncAttributeMaxDynamicSharedMemorySize, SM_BYTES);
    cudaFuncSetAttribute(mma_gemm<EPI_BIASRES>, cudaFuncAttributeMaxDynamicSharedMemorySize, SM_BYTES);
    cudaFuncSetAttribute(mma_gemm<EPI_GELU>,    cudaFuncAttributeMaxDynamicSharedMemorySize, SM_BYTES);
    cudaFuncSetAttribute(fa_kernel,             cudaFuncAttributeMaxDynamicSharedMemorySize, ATT_BYTES);

    // 0) round weights to tf32 once
    round_w<<<1024, 256>>>((const float4*)wq,    (float4*)wq_r, 262144);
    round_w<<<1024, 256>>>((const float4*)wk,    (float4*)wk_r, 262144);
    round_w<<<1024, 256>>>((const float4*)wv,    (float4*)wv_r, 262144);
    round_w<<<1024, 256>>>((const float4*)w_out, (float4*)wo_r, 262144);
    round_w<<<4096, 256>>>((const float4*)w1,    (float4*)w1_r, 1048576);
    round_w<<<4096, 256>>>((const float4*)w2,    (float4*)w2_r, 1048576);

    // 1) LN1 (tf32-rounded output)
    ln_kernel<<<NTOK, 256>>>(x, ln1_s, ln1_b, xn);

    // 2) QKV projections with head-split store (tf32-rounded)
    dim3 gproj(DIM / 128, NTOK / 128);
    mma_gemm<EPI_QKV><<<gproj, 256, SM_BYTES>>>(xn, wq_r, nullptr, nullptr, q, NTOK, DIM, DIM);
    mma_gemm<EPI_QKV><<<gproj, 256, SM_BYTES>>>(xn, wk_r, nullptr, nullptr, k, NTOK, DIM, DIM);
    mma_gemm<EPI_QKV><<<gproj, 256, SM_BYTES>>>(xn, wv_r, nullptr, nullptr, v, NTOK, DIM, DIM);

    // 3) causal flash attention (tensor cores)
    dim3 gattn(BATCH * NHEAD, SEQ / 64);
    fa_kernel<<<gattn, 128, ATT_BYTES>>>(q, k, v, ctx);

    // 4) out projection + bias + residual(x)
    mma_gemm<EPI_BIASRES><<<gproj, 256, SM_BYTES>>>(ctx, wo_r, b_out, x, res1, NTOK, DIM, DIM);

    // 5) LN2
    ln_kernel<<<NTOK, 256>>>(res1, ln2_s, ln2_b, xn2);

    // 6) MLP up + GELU (tf32-rounded output)
    dim3 gup(FF / 128, NTOK / 128);
    mma_gemm<EPI_GELU><<<gup, 256, SM_BYTES>>>(xn2, w1_r, b1, nullptr, h1, NTOK, FF, DIM);

    // 7) MLP down + bias + residual(res1) -> out
    mma_gemm<EPI_BIASRES><<<gproj, 256, SM_BYTES>>>(h1, w2_r, b2, res1, out, NTOK, DIM, FF);
}